// round 6
// baseline (speedup 1.0000x reference)
#include <cuda_runtime.h>
#include <cuda_fp16.h>

#define IN_F 256
#define NHEAD 8
#define OUT_F 64
#define TMAX 8
#define MAXN 100000

// Scratch (static __device__ — no allocations allowed)
__device__ float g_A[IN_F * 16];        // [i][0..7]=A_l, [i][8..15]=A_r
__device__ float g_ee[TMAX * NHEAD];    // per-etype logit table
// el/er stored as fp16: 16B per node record (8 halfs), read as uint2 (4 halfs/thread)
__device__ uint2 g_elh[MAXN * 2];
__device__ uint2 g_erh[MAXN * 2];
// softmax denominator, fp32 (atomic target), 32B per node record
__device__ float4 g_s4[MAXN * 2];

// ---------------------------------------------------------------------------
// K1: setup — fold attn_l/attn_r into W_fc (blocks 0..255, one per input row i)
//     and build the TxH edge-type logit table (blocks 256..263, one per t).
// ---------------------------------------------------------------------------
__global__ void setup(const float* __restrict__ W_fc,
                      const float* __restrict__ attn_l,
                      const float* __restrict__ attn_r,
                      const float* __restrict__ edge_emb,
                      const float* __restrict__ W_e,
                      const float* __restrict__ attn_e) {
    int h = threadIdx.x >> 5;
    int lane = threadIdx.x & 31;
    if (blockIdx.x < IN_F) {
        int i = blockIdx.x;
        const float* wrow = W_fc + (size_t)i * (NHEAD * OUT_F) + h * OUT_F;
        const float* al = attn_l + h * OUT_F;
        const float* ar = attn_r + h * OUT_F;
        float sl = wrow[lane] * al[lane] + wrow[lane + 32] * al[lane + 32];
        float sr = wrow[lane] * ar[lane] + wrow[lane + 32] * ar[lane + 32];
#pragma unroll
        for (int o = 16; o; o >>= 1) {
            sl += __shfl_xor_sync(0xFFFFFFFFu, sl, o);
            sr += __shfl_xor_sync(0xFFFFFFFFu, sr, o);
        }
        if (lane == 0) {
            g_A[i * 16 + h] = sl;
            g_A[i * 16 + 8 + h] = sr;
        }
    } else {
        int t = blockIdx.x - IN_F;
        float acc = 0.0f;
#pragma unroll
        for (int j = 0; j < 2; j++) {
            int f = lane + j * 32;
            float proj = 0.0f;
#pragma unroll 8
            for (int g = 0; g < 64; g++)
                proj += edge_emb[t * 64 + g] * W_e[(size_t)g * (NHEAD * 64) + h * 64 + f];
            acc += proj * attn_e[h * 64 + f];
        }
#pragma unroll
        for (int o = 16; o; o >>= 1)
            acc += __shfl_xor_sync(0xFFFFFFFFu, acc, o);
        if (lane == 0) g_ee[t * NHEAD + h] = acc;
    }
}

// ---------------------------------------------------------------------------
// K2: node projection el/er = feat @ [A_l | A_r]   ([N,256] @ [256,16]).
// Accumulates fp32, stores el/er as fp16 records (one rounding; err ~5e-4 rel
// on ~0.08-magnitude logits -> ~1e-4 on output). Also zeroes g_s4.
// ---------------------------------------------------------------------------
__global__ void __launch_bounds__(128) node_proj(const float* __restrict__ feat, int N) {
    __shared__ float sA[IN_F * 16];     // 16 KB
    __shared__ float sF[4][32][32];     // 16 KB, XOR-swizzled
    int tid = threadIdx.x;
    for (int i = tid; i < IN_F * 16; i += 128) sA[i] = g_A[i];
    int w = tid >> 5, lane = tid & 31;
    int nodeBase = blockIdx.x * 128 + w * 32;
    int myNode = nodeBase + lane;
    float accl[8] = {0, 0, 0, 0, 0, 0, 0, 0};
    float accr[8] = {0, 0, 0, 0, 0, 0, 0, 0};
    __syncthreads();

    for (int kc = 0; kc < IN_F; kc += 32) {
#pragma unroll
        for (int r = 0; r < 32; r++) {
            int row = nodeBase + r;
            if (row > N - 1) row = N - 1;
            sF[w][r][(lane + r) & 31] = feat[(size_t)row * IN_F + kc + lane];
        }
        __syncwarp();
#pragma unroll 8
        for (int k = 0; k < 32; k++) {
            float f = sF[w][lane][(k + lane) & 31];
            const float4* ap = (const float4*)&sA[(kc + k) * 16];
            float4 a0 = ap[0], a1 = ap[1], a2 = ap[2], a3 = ap[3];
            accl[0] += f * a0.x; accl[1] += f * a0.y; accl[2] += f * a0.z; accl[3] += f * a0.w;
            accl[4] += f * a1.x; accl[5] += f * a1.y; accl[6] += f * a1.z; accl[7] += f * a1.w;
            accr[0] += f * a2.x; accr[1] += f * a2.y; accr[2] += f * a2.z; accr[3] += f * a2.w;
            accr[4] += f * a3.x; accr[5] += f * a3.y; accr[6] += f * a3.z; accr[7] += f * a3.w;
        }
        __syncwarp();
    }
    if (myNode < N) {
        __half2 l01 = __floats2half2_rn(accl[0], accl[1]);
        __half2 l23 = __floats2half2_rn(accl[2], accl[3]);
        __half2 l45 = __floats2half2_rn(accl[4], accl[5]);
        __half2 l67 = __floats2half2_rn(accl[6], accl[7]);
        uint2 u0, u1;
        u0.x = *(unsigned*)&l01; u0.y = *(unsigned*)&l23;
        u1.x = *(unsigned*)&l45; u1.y = *(unsigned*)&l67;
        g_elh[(size_t)myNode * 2]     = u0;
        g_elh[(size_t)myNode * 2 + 1] = u1;
        __half2 r01 = __floats2half2_rn(accr[0], accr[1]);
        __half2 r23 = __floats2half2_rn(accr[2], accr[3]);
        __half2 r45 = __floats2half2_rn(accr[4], accr[5]);
        __half2 r67 = __floats2half2_rn(accr[6], accr[7]);
        uint2 v0, v1;
        v0.x = *(unsigned*)&r01; v0.y = *(unsigned*)&r23;
        v1.x = *(unsigned*)&r45; v1.y = *(unsigned*)&r67;
        g_erh[(size_t)myNode * 2]     = v0;
        g_erh[(size_t)myNode * 2 + 1] = v1;
        float4 z = make_float4(0.f, 0.f, 0.f, 0.f);
        g_s4[(size_t)myNode * 2]     = z;
        g_s4[(size_t)myNode * 2 + 1] = z;
    }
}

// ---------------------------------------------------------------------------
// K3: 2 threads per edge, 4 heads each. One LDG.64 per table per thread
// (16B/edge/table scattered — minimum). Accumulate s via red.global.add.v4.
// Max-shift dropped (softmax shift-invariant; e = relu(..) in [0,~2]).
// ---------------------------------------------------------------------------
__global__ void __launch_bounds__(256) edge_expsum(const int* __restrict__ et,
                                                   const int* __restrict__ src,
                                                   const int* __restrict__ dst,
                                                   int E) {
    __shared__ __align__(16) float see[TMAX * NHEAD];
    if (threadIdx.x < TMAX * NHEAD) see[threadIdx.x] = g_ee[threadIdx.x];
    __syncthreads();
    int idx = blockIdx.x * 256 + threadIdx.x;
    int e = idx >> 1;
    int sub = idx & 1;
    if (e >= E) return;
    int s = src[e];
    int d = dst[e];
    int t = et[e];
    uint2 lu = __ldg(&g_elh[(size_t)s * 2 + sub]);
    uint2 ru = __ldg(&g_erh[(size_t)d * 2 + sub]);
    float2 l0 = __half22float2(*(__half2*)&lu.x);
    float2 l1 = __half22float2(*(__half2*)&lu.y);
    float2 r0 = __half22float2(*(__half2*)&ru.x);
    float2 r1 = __half22float2(*(__half2*)&ru.y);
    float4 b = *(const float4*)(see + t * 8 + sub * 4);
    float x0 = __expf(fmaxf(l0.x + r0.x + b.x, 0.0f));
    float x1 = __expf(fmaxf(l0.y + r0.y + b.y, 0.0f));
    float x2 = __expf(fmaxf(l1.x + r1.x + b.z, 0.0f));
    float x3 = __expf(fmaxf(l1.y + r1.y + b.w, 0.0f));
    float* sp = (float*)&g_s4[(size_t)d * 2 + sub];
    asm volatile("red.global.add.v4.f32 [%0], {%1,%2,%3,%4};"
                 :: "l"(sp), "f"(x0), "f"(x1), "f"(x2), "f"(x3) : "memory");
}

// ---------------------------------------------------------------------------
// K4: recompute ex (tables are L2-resident) and write out = ex / s[dst].
// Loads per thread: el 8B, er 8B, s 16B; store 16B contiguous (STG.128).
// ---------------------------------------------------------------------------
__global__ void __launch_bounds__(256) edge_out(const int* __restrict__ et,
                                                const int* __restrict__ src,
                                                const int* __restrict__ dst,
                                                float* __restrict__ out,
                                                int E) {
    __shared__ __align__(16) float see[TMAX * NHEAD];
    if (threadIdx.x < TMAX * NHEAD) see[threadIdx.x] = g_ee[threadIdx.x];
    __syncthreads();
    int idx = blockIdx.x * 256 + threadIdx.x;
    int e = idx >> 1;
    int sub = idx & 1;
    if (e >= E) return;
    int s = src[e];
    int d = dst[e];
    int t = et[e];
    uint2 lu = __ldg(&g_elh[(size_t)s * 2 + sub]);
    uint2 ru = __ldg(&g_erh[(size_t)d * 2 + sub]);
    float4 sv = __ldg(&g_s4[(size_t)d * 2 + sub]);
    float2 l0 = __half22float2(*(__half2*)&lu.x);
    float2 l1 = __half22float2(*(__half2*)&lu.y);
    float2 r0 = __half22float2(*(__half2*)&ru.x);
    float2 r1 = __half22float2(*(__half2*)&ru.y);
    float4 b = *(const float4*)(see + t * 8 + sub * 4);
    float4 o;
    o.x = __fdividef(__expf(fmaxf(l0.x + r0.x + b.x, 0.0f)), sv.x);
    o.y = __fdividef(__expf(fmaxf(l0.y + r0.y + b.y, 0.0f)), sv.y);
    o.z = __fdividef(__expf(fmaxf(l1.x + r1.x + b.z, 0.0f)), sv.z);
    o.w = __fdividef(__expf(fmaxf(l1.y + r1.y + b.w, 0.0f)), sv.w);
    *(float4*)(out + (size_t)e * 8 + sub * 4) = o;
}

// ---------------------------------------------------------------------------
extern "C" void kernel_launch(void* const* d_in, const int* in_sizes, int n_in,
                              void* d_out, int out_size) {
    const float* feat     = (const float*)d_in[0];
    const int*   etype    = (const int*)  d_in[1];
    const int*   src      = (const int*)  d_in[2];
    const int*   dst      = (const int*)  d_in[3];
    const float* W_fc     = (const float*)d_in[4];
    const float* edge_emb = (const float*)d_in[5];
    const float* W_e      = (const float*)d_in[6];
    const float* attn_l   = (const float*)d_in[7];
    const float* attn_r   = (const float*)d_in[8];
    const float* attn_e   = (const float*)d_in[9];
    float* out = (float*)d_out;

    int N = in_sizes[0] / IN_F;
    int E = in_sizes[1];

    setup<<<IN_F + TMAX, 256>>>(W_fc, attn_l, attn_r, edge_emb, W_e, attn_e);
    node_proj<<<(N + 127) / 128, 128>>>(feat, N);
    int ethreads = E * 2;
    edge_expsum<<<(ethreads + 255) / 256, 256>>>(etype, src, dst, E);
    edge_out<<<(ethreads + 255) / 256, 256>>>(etype, src, dst, out, E);
}

// round 8
// speedup vs baseline: 1.2063x; 1.2063x over previous
#include <cuda_runtime.h>
#include <cuda_fp16.h>

#define IN_F 256
#define NHEAD 8
#define OUT_F 64
#define TMAX 8
#define MAXN 100000
#define MAXE 3200000

typedef unsigned long long ull;

// Scratch (static __device__ — no allocations allowed)
__device__ float g_A[IN_F * 16];        // [i][0..7]=A_l, [i][8..15]=A_r
__device__ float g_ee[TMAX * NHEAD];    // per-etype logit table
// el/er stored as fp16: 16B per node record (8 halfs), read as uint2 (4 halfs/thread)
__device__ uint2 g_elh[MAXN * 2];
__device__ uint2 g_erh[MAXN * 2];
// softmax denominator, fp32 (atomic target), 32B per node record
__device__ float4 g_s4[MAXN * 2];
// persisted exp(relu(logit)) per edge, fp16 x8 = 16B/edge (2 ulls), coalesced
__device__ ull g_ex[MAXE * 2];

// ---------------------------------------------------------------------------
// K1: setup — fold attn_l/attn_r into W_fc (blocks 0..255, one per input row i)
//     and build the TxH edge-type logit table (blocks 256..263, one per t).
// ---------------------------------------------------------------------------
__global__ void setup(const float* __restrict__ W_fc,
                      const float* __restrict__ attn_l,
                      const float* __restrict__ attn_r,
                      const float* __restrict__ edge_emb,
                      const float* __restrict__ W_e,
                      const float* __restrict__ attn_e) {
    int h = threadIdx.x >> 5;
    int lane = threadIdx.x & 31;
    if (blockIdx.x < IN_F) {
        int i = blockIdx.x;
        const float* wrow = W_fc + (size_t)i * (NHEAD * OUT_F) + h * OUT_F;
        const float* al = attn_l + h * OUT_F;
        const float* ar = attn_r + h * OUT_F;
        float sl = wrow[lane] * al[lane] + wrow[lane + 32] * al[lane + 32];
        float sr = wrow[lane] * ar[lane] + wrow[lane + 32] * ar[lane + 32];
#pragma unroll
        for (int o = 16; o; o >>= 1) {
            sl += __shfl_xor_sync(0xFFFFFFFFu, sl, o);
            sr += __shfl_xor_sync(0xFFFFFFFFu, sr, o);
        }
        if (lane == 0) {
            g_A[i * 16 + h] = sl;
            g_A[i * 16 + 8 + h] = sr;
        }
    } else {
        int t = blockIdx.x - IN_F;
        float acc = 0.0f;
#pragma unroll
        for (int j = 0; j < 2; j++) {
            int f = lane + j * 32;
            float proj = 0.0f;
#pragma unroll 8
            for (int g = 0; g < 64; g++)
                proj += edge_emb[t * 64 + g] * W_e[(size_t)g * (NHEAD * 64) + h * 64 + f];
            acc += proj * attn_e[h * 64 + f];
        }
#pragma unroll
        for (int o = 16; o; o >>= 1)
            acc += __shfl_xor_sync(0xFFFFFFFFu, acc, o);
        if (lane == 0) g_ee[t * NHEAD + h] = acc;
    }
}

// ---------------------------------------------------------------------------
// K2: node projection el/er = feat @ [A_l | A_r]   ([N,256] @ [256,16]).
// Inner product uses packed fma.rn.f32x2 (2 MACs per FMA-pipe slot; ptxas
// never auto-fuses this). A pairs are adjacent in smem -> longlong2 loads
// feed the packed FMAs directly. Stores el/er fp16; zeroes g_s4.
// ---------------------------------------------------------------------------
__global__ void __launch_bounds__(128) node_proj(const float* __restrict__ feat, int N) {
    __shared__ __align__(16) float sA[IN_F * 16];   // 16 KB
    __shared__ float sF[4][32][32];                 // 16 KB, XOR-swizzled
    int tid = threadIdx.x;
    for (int i = tid; i < IN_F * 16; i += 128) sA[i] = g_A[i];
    int w = tid >> 5, lane = tid & 31;
    int nodeBase = blockIdx.x * 128 + w * 32;
    int myNode = nodeBase + lane;
    ull acc[8];                                     // 8 packed f32x2 accumulators
#pragma unroll
    for (int j = 0; j < 8; j++) acc[j] = 0ULL;      // (0.f,0.f)
    __syncthreads();

    for (int kc = 0; kc < IN_F; kc += 32) {
#pragma unroll
        for (int r = 0; r < 32; r++) {
            int row = nodeBase + r;
            if (row > N - 1) row = N - 1;
            sF[w][r][(lane + r) & 31] = feat[(size_t)row * IN_F + kc + lane];
        }
        __syncwarp();
#pragma unroll 8
        for (int k = 0; k < 32; k++) {
            float f = sF[w][lane][(k + lane) & 31];
            ull fb;
            asm("mov.b64 %0, {%1, %1};" : "=l"(fb) : "f"(f));
            const longlong2* ap = (const longlong2*)&sA[(kc + k) * 16];
            longlong2 q0 = ap[0], q1 = ap[1], q2 = ap[2], q3 = ap[3];
            asm("fma.rn.f32x2 %0, %1, %2, %0;" : "+l"(acc[0]) : "l"(fb), "l"((ull)q0.x));
            asm("fma.rn.f32x2 %0, %1, %2, %0;" : "+l"(acc[1]) : "l"(fb), "l"((ull)q0.y));
            asm("fma.rn.f32x2 %0, %1, %2, %0;" : "+l"(acc[2]) : "l"(fb), "l"((ull)q1.x));
            asm("fma.rn.f32x2 %0, %1, %2, %0;" : "+l"(acc[3]) : "l"(fb), "l"((ull)q1.y));
            asm("fma.rn.f32x2 %0, %1, %2, %0;" : "+l"(acc[4]) : "l"(fb), "l"((ull)q2.x));
            asm("fma.rn.f32x2 %0, %1, %2, %0;" : "+l"(acc[5]) : "l"(fb), "l"((ull)q2.y));
            asm("fma.rn.f32x2 %0, %1, %2, %0;" : "+l"(acc[6]) : "l"(fb), "l"((ull)q3.x));
            asm("fma.rn.f32x2 %0, %1, %2, %0;" : "+l"(acc[7]) : "l"(fb), "l"((ull)q3.y));
        }
        __syncwarp();
    }
    if (myNode < N) {
        float v[16];
#pragma unroll
        for (int j = 0; j < 8; j++)
            asm("mov.b64 {%0, %1}, %2;" : "=f"(v[2 * j]), "=f"(v[2 * j + 1]) : "l"(acc[j]));
        __half2 l01 = __floats2half2_rn(v[0], v[1]);
        __half2 l23 = __floats2half2_rn(v[2], v[3]);
        __half2 l45 = __floats2half2_rn(v[4], v[5]);
        __half2 l67 = __floats2half2_rn(v[6], v[7]);
        uint2 u0, u1;
        u0.x = *(unsigned*)&l01; u0.y = *(unsigned*)&l23;
        u1.x = *(unsigned*)&l45; u1.y = *(unsigned*)&l67;
        g_elh[(size_t)myNode * 2]     = u0;
        g_elh[(size_t)myNode * 2 + 1] = u1;
        __half2 r01 = __floats2half2_rn(v[8], v[9]);
        __half2 r23 = __floats2half2_rn(v[10], v[11]);
        __half2 r45 = __floats2half2_rn(v[12], v[13]);
        __half2 r67 = __floats2half2_rn(v[14], v[15]);
        uint2 w0, w1;
        w0.x = *(unsigned*)&r01; w0.y = *(unsigned*)&r23;
        w1.x = *(unsigned*)&r45; w1.y = *(unsigned*)&r67;
        g_erh[(size_t)myNode * 2]     = w0;
        g_erh[(size_t)myNode * 2 + 1] = w1;
        float4 z = make_float4(0.f, 0.f, 0.f, 0.f);
        g_s4[(size_t)myNode * 2]     = z;
        g_s4[(size_t)myNode * 2 + 1] = z;
    }
}

// ---------------------------------------------------------------------------
// K3: 2 threads per edge, 4 heads each. Gathers el[src], er[dst]; accumulates
// s via red.global.add.v4; ALSO persists ex as fp16x4 (8B coalesced store) so
// the finalize pass never re-gathers el/er. Max-shift dropped (softmax is
// shift-invariant; logits in [0,~0.8], no overflow).
// ---------------------------------------------------------------------------
__global__ void __launch_bounds__(256) edge_expsum(const int* __restrict__ et,
                                                   const int* __restrict__ src,
                                                   const int* __restrict__ dst,
                                                   int E) {
    __shared__ __align__(16) float see[TMAX * NHEAD];
    if (threadIdx.x < TMAX * NHEAD) see[threadIdx.x] = g_ee[threadIdx.x];
    __syncthreads();
    int idx = blockIdx.x * 256 + threadIdx.x;
    int e = idx >> 1;
    int sub = idx & 1;
    if (e >= E) return;
    int s = src[e];
    int d = dst[e];
    int t = et[e];
    uint2 lu = __ldg(&g_elh[(size_t)s * 2 + sub]);
    uint2 ru = __ldg(&g_erh[(size_t)d * 2 + sub]);
    float2 l0 = __half22float2(*(__half2*)&lu.x);
    float2 l1 = __half22float2(*(__half2*)&lu.y);
    float2 r0 = __half22float2(*(__half2*)&ru.x);
    float2 r1 = __half22float2(*(__half2*)&ru.y);
    float4 b = *(const float4*)(see + t * 8 + sub * 4);
    float x0 = __expf(fmaxf(l0.x + r0.x + b.x, 0.0f));
    float x1 = __expf(fmaxf(l0.y + r0.y + b.y, 0.0f));
    float x2 = __expf(fmaxf(l1.x + r1.x + b.z, 0.0f));
    float x3 = __expf(fmaxf(l1.y + r1.y + b.w, 0.0f));
    float* sp = (float*)&g_s4[(size_t)d * 2 + sub];
    asm volatile("red.global.add.v4.f32 [%0], {%1,%2,%3,%4};"
                 :: "l"(sp), "f"(x0), "f"(x1), "f"(x2), "f"(x3) : "memory");
    __half2 h01 = __floats2half2_rn(x0, x1);
    __half2 h23 = __floats2half2_rn(x2, x3);
    ull packed;
    asm("mov.b64 %0, {%1, %2};" : "=l"(packed)
        : "r"(*(unsigned*)&h01), "r"(*(unsigned*)&h23));
    g_ex[(size_t)idx] = packed;   // idx = e*2+sub, fully coalesced
}

// ---------------------------------------------------------------------------
// K4 (finalize): out = ex / s[dst]. Pure streaming except ONE 16B gather per
// thread (s[dst]). No exp, no etype/src, no smem.
// ---------------------------------------------------------------------------
__global__ void __launch_bounds__(256) finalize(const int* __restrict__ dst,
                                                float* __restrict__ out,
                                                int E) {
    int idx = blockIdx.x * 256 + threadIdx.x;
    int e = idx >> 1;
    int sub = idx & 1;
    if (e >= E) return;
    int d = dst[e];
    ull packed = g_ex[(size_t)idx];
    float4 sv = __ldg(&g_s4[(size_t)d * 2 + sub]);
    unsigned lo, hi;
    asm("mov.b64 {%0, %1}, %2;" : "=r"(lo), "=r"(hi) : "l"(packed));
    float2 x01 = __half22float2(*(__half2*)&lo);
    float2 x23 = __half22float2(*(__half2*)&hi);
    float4 o;
    o.x = __fdividef(x01.x, sv.x);
    o.y = __fdividef(x01.y, sv.y);
    o.z = __fdividef(x23.x, sv.z);
    o.w = __fdividef(x23.y, sv.w);
    *(float4*)(out + (size_t)e * 8 + sub * 4) = o;
}

// ---------------------------------------------------------------------------
extern "C" void kernel_launch(void* const* d_in, const int* in_sizes, int n_in,
                              void* d_out, int out_size) {
    const float* feat     = (const float*)d_in[0];
    const int*   etype    = (const int*)  d_in[1];
    const int*   src      = (const int*)  d_in[2];
    const int*   dst      = (const int*)  d_in[3];
    const float* W_fc     = (const float*)d_in[4];
    const float* edge_emb = (const float*)d_in[5];
    const float* W_e      = (const float*)d_in[6];
    const float* attn_l   = (const float*)d_in[7];
    const float* attn_r   = (const float*)d_in[8];
    const float* attn_e   = (const float*)d_in[9];
    float* out = (float*)d_out;

    int N = in_sizes[0] / IN_F;
    int E = in_sizes[1];

    setup<<<IN_F + TMAX, 256>>>(W_fc, attn_l, attn_r, edge_emb, W_e, attn_e);
    node_proj<<<(N + 127) / 128, 128>>>(feat, N);
    int ethreads = E * 2;
    edge_expsum<<<(ethreads + 255) / 256, 256>>>(etype, src, dst, E);
    finalize<<<(ethreads + 255) / 256, 256>>>(dst, out, E);
}

// round 9
// speedup vs baseline: 1.2596x; 1.0441x over previous
#include <cuda_runtime.h>
#include <cuda_fp16.h>

#define IN_F 256
#define NHEAD 8
#define OUT_F 64
#define TMAX 8
#define MAXN 100000
#define MAXE 3200000

typedef unsigned long long ull;

// Scratch (static __device__ — no allocations allowed)
__device__ float g_A[IN_F * 16];        // [i][0..7]=A_l, [i][8..15]=A_r
__device__ float g_ee[TMAX * NHEAD];    // per-etype logit table
// el/er as fp16: one 16B record per node (8 halfs), read as a single LDG.128
__device__ uint4 g_elh[MAXN];
__device__ uint4 g_erh[MAXN];
// softmax denominator, fp32 (atomic target), 32B per node record
__device__ float4 g_s4[MAXN * 2];
// persisted exp(relu(logit)) per edge, fp16 x8 = 16B/edge, coalesced
__device__ ulonglong2 g_ex[MAXE];

// ---------------------------------------------------------------------------
// K1: setup — fold attn_l/attn_r into W_fc (blocks 0..255, one per input row i)
//     and build the TxH edge-type logit table (blocks 256..263, one per t).
// ---------------------------------------------------------------------------
__global__ void setup(const float* __restrict__ W_fc,
                      const float* __restrict__ attn_l,
                      const float* __restrict__ attn_r,
                      const float* __restrict__ edge_emb,
                      const float* __restrict__ W_e,
                      const float* __restrict__ attn_e) {
    int h = threadIdx.x >> 5;
    int lane = threadIdx.x & 31;
    if (blockIdx.x < IN_F) {
        int i = blockIdx.x;
        const float* wrow = W_fc + (size_t)i * (NHEAD * OUT_F) + h * OUT_F;
        const float* al = attn_l + h * OUT_F;
        const float* ar = attn_r + h * OUT_F;
        float sl = wrow[lane] * al[lane] + wrow[lane + 32] * al[lane + 32];
        float sr = wrow[lane] * ar[lane] + wrow[lane + 32] * ar[lane + 32];
#pragma unroll
        for (int o = 16; o; o >>= 1) {
            sl += __shfl_xor_sync(0xFFFFFFFFu, sl, o);
            sr += __shfl_xor_sync(0xFFFFFFFFu, sr, o);
        }
        if (lane == 0) {
            g_A[i * 16 + h] = sl;
            g_A[i * 16 + 8 + h] = sr;
        }
    } else {
        int t = blockIdx.x - IN_F;
        float acc = 0.0f;
#pragma unroll
        for (int j = 0; j < 2; j++) {
            int f = lane + j * 32;
            float proj = 0.0f;
#pragma unroll 8
            for (int g = 0; g < 64; g++)
                proj += edge_emb[t * 64 + g] * W_e[(size_t)g * (NHEAD * 64) + h * 64 + f];
            acc += proj * attn_e[h * 64 + f];
        }
#pragma unroll
        for (int o = 16; o; o >>= 1)
            acc += __shfl_xor_sync(0xFFFFFFFFu, acc, o);
        if (lane == 0) g_ee[t * NHEAD + h] = acc;
    }
}

// ---------------------------------------------------------------------------
// K2: node projection el/er = feat @ [A_l | A_r]   ([N,256] @ [256,16]).
// 2 nodes per thread: the 4 broadcast sA LDS.128 per k-step are amortized over
// 32 MACs (was 16) — 6 LDS / 32 MACs vs 10 / 32. Packed fma.rn.f32x2 keeps
// FMA-pipe slots at 2 MACs each. Stores fp16 records; zeroes g_s4.
// ---------------------------------------------------------------------------
__global__ void __launch_bounds__(128) node_proj(const float* __restrict__ feat, int N) {
    __shared__ __align__(16) float sA[IN_F * 16];   // 16 KB
    __shared__ float sF[4][64][32];                 // 32 KB, XOR-swizzled
    int tid = threadIdx.x;
    for (int i = tid; i < IN_F * 16; i += 128) sA[i] = g_A[i];
    int w = tid >> 5, lane = tid & 31;
    int warpBase = blockIdx.x * 256 + w * 64;       // 64 nodes per warp
    ull acc0[8], acc1[8];                           // 2 nodes x 8 packed f32x2
#pragma unroll
    for (int j = 0; j < 8; j++) { acc0[j] = 0ULL; acc1[j] = 0ULL; }
    __syncthreads();

    for (int kc = 0; kc < IN_F; kc += 32) {
#pragma unroll 16
        for (int r = 0; r < 64; r++) {
            int row = warpBase + r;
            if (row > N - 1) row = N - 1;
            sF[w][r][(lane + r) & 31] = feat[(size_t)row * IN_F + kc + lane];
        }
        __syncwarp();
#pragma unroll 8
        for (int k = 0; k < 32; k++) {
            int col = (k + lane) & 31;
            float f0 = sF[w][lane][col];
            float f1 = sF[w][lane + 32][col];
            ull fb0, fb1;
            asm("mov.b64 %0, {%1, %1};" : "=l"(fb0) : "f"(f0));
            asm("mov.b64 %0, {%1, %1};" : "=l"(fb1) : "f"(f1));
            const longlong2* ap = (const longlong2*)&sA[(kc + k) * 16];
            longlong2 q0 = ap[0], q1 = ap[1], q2 = ap[2], q3 = ap[3];
            asm("fma.rn.f32x2 %0, %1, %2, %0;" : "+l"(acc0[0]) : "l"(fb0), "l"((ull)q0.x));
            asm("fma.rn.f32x2 %0, %1, %2, %0;" : "+l"(acc0[1]) : "l"(fb0), "l"((ull)q0.y));
            asm("fma.rn.f32x2 %0, %1, %2, %0;" : "+l"(acc0[2]) : "l"(fb0), "l"((ull)q1.x));
            asm("fma.rn.f32x2 %0, %1, %2, %0;" : "+l"(acc0[3]) : "l"(fb0), "l"((ull)q1.y));
            asm("fma.rn.f32x2 %0, %1, %2, %0;" : "+l"(acc0[4]) : "l"(fb0), "l"((ull)q2.x));
            asm("fma.rn.f32x2 %0, %1, %2, %0;" : "+l"(acc0[5]) : "l"(fb0), "l"((ull)q2.y));
            asm("fma.rn.f32x2 %0, %1, %2, %0;" : "+l"(acc0[6]) : "l"(fb0), "l"((ull)q3.x));
            asm("fma.rn.f32x2 %0, %1, %2, %0;" : "+l"(acc0[7]) : "l"(fb0), "l"((ull)q3.y));
            asm("fma.rn.f32x2 %0, %1, %2, %0;" : "+l"(acc1[0]) : "l"(fb1), "l"((ull)q0.x));
            asm("fma.rn.f32x2 %0, %1, %2, %0;" : "+l"(acc1[1]) : "l"(fb1), "l"((ull)q0.y));
            asm("fma.rn.f32x2 %0, %1, %2, %0;" : "+l"(acc1[2]) : "l"(fb1), "l"((ull)q1.x));
            asm("fma.rn.f32x2 %0, %1, %2, %0;" : "+l"(acc1[3]) : "l"(fb1), "l"((ull)q1.y));
            asm("fma.rn.f32x2 %0, %1, %2, %0;" : "+l"(acc1[4]) : "l"(fb1), "l"((ull)q2.x));
            asm("fma.rn.f32x2 %0, %1, %2, %0;" : "+l"(acc1[5]) : "l"(fb1), "l"((ull)q2.y));
            asm("fma.rn.f32x2 %0, %1, %2, %0;" : "+l"(acc1[6]) : "l"(fb1), "l"((ull)q3.x));
            asm("fma.rn.f32x2 %0, %1, %2, %0;" : "+l"(acc1[7]) : "l"(fb1), "l"((ull)q3.y));
        }
        __syncwarp();
    }
#pragma unroll
    for (int nn = 0; nn < 2; nn++) {
        int myNode = warpBase + lane + nn * 32;
        ull* acc = nn ? acc1 : acc0;
        if (myNode < N) {
            float v[16];
#pragma unroll
            for (int j = 0; j < 8; j++)
                asm("mov.b64 {%0, %1}, %2;" : "=f"(v[2 * j]), "=f"(v[2 * j + 1]) : "l"(acc[j]));
            __half2 l01 = __floats2half2_rn(v[0], v[1]);
            __half2 l23 = __floats2half2_rn(v[2], v[3]);
            __half2 l45 = __floats2half2_rn(v[4], v[5]);
            __half2 l67 = __floats2half2_rn(v[6], v[7]);
            uint4 u;
            u.x = *(unsigned*)&l01; u.y = *(unsigned*)&l23;
            u.z = *(unsigned*)&l45; u.w = *(unsigned*)&l67;
            g_elh[myNode] = u;
            __half2 r01 = __floats2half2_rn(v[8], v[9]);
            __half2 r23 = __floats2half2_rn(v[10], v[11]);
            __half2 r45 = __floats2half2_rn(v[12], v[13]);
            __half2 r67 = __floats2half2_rn(v[14], v[15]);
            uint4 q;
            q.x = *(unsigned*)&r01; q.y = *(unsigned*)&r23;
            q.z = *(unsigned*)&r45; q.w = *(unsigned*)&r67;
            g_erh[myNode] = q;
            float4 z = make_float4(0.f, 0.f, 0.f, 0.f);
            g_s4[(size_t)myNode * 2]     = z;
            g_s4[(size_t)myNode * 2 + 1] = z;
        }
    }
}

// ---------------------------------------------------------------------------
// K3: 1 thread per edge, all 8 heads. Gathers are single LDG.128 per table;
// indices loaded exactly once. Accumulate s via 2x red.global.add.v4; persist
// ex as one STG.128 (fp16x8). Max-shift dropped (softmax shift-invariant;
// logits in [0,~0.8], no overflow).
// ---------------------------------------------------------------------------
__global__ void __launch_bounds__(256) edge_expsum(const int* __restrict__ et,
                                                   const int* __restrict__ src,
                                                   const int* __restrict__ dst,
                                                   int E) {
    __shared__ __align__(16) float see[TMAX * NHEAD];
    if (threadIdx.x < TMAX * NHEAD) see[threadIdx.x] = g_ee[threadIdx.x];
    __syncthreads();
    int e = blockIdx.x * 256 + threadIdx.x;
    if (e >= E) return;
    int s = src[e];
    int d = dst[e];
    int t = et[e];
    uint4 lu = __ldg(&g_elh[s]);
    uint4 ru = __ldg(&g_erh[d]);
    float2 l0 = __half22float2(*(__half2*)&lu.x);
    float2 l1 = __half22float2(*(__half2*)&lu.y);
    float2 l2 = __half22float2(*(__half2*)&lu.z);
    float2 l3 = __half22float2(*(__half2*)&lu.w);
    float2 r0 = __half22float2(*(__half2*)&ru.x);
    float2 r1 = __half22float2(*(__half2*)&ru.y);
    float2 r2 = __half22float2(*(__half2*)&ru.z);
    float2 r3 = __half22float2(*(__half2*)&ru.w);
    float4 b0 = *(const float4*)(see + t * 8);
    float4 b1 = *(const float4*)(see + t * 8 + 4);
    float x0 = __expf(fmaxf(l0.x + r0.x + b0.x, 0.0f));
    float x1 = __expf(fmaxf(l0.y + r0.y + b0.y, 0.0f));
    float x2 = __expf(fmaxf(l1.x + r1.x + b0.z, 0.0f));
    float x3 = __expf(fmaxf(l1.y + r1.y + b0.w, 0.0f));
    float x4 = __expf(fmaxf(l2.x + r2.x + b1.x, 0.0f));
    float x5 = __expf(fmaxf(l2.y + r2.y + b1.y, 0.0f));
    float x6 = __expf(fmaxf(l3.x + r3.x + b1.z, 0.0f));
    float x7 = __expf(fmaxf(l3.y + r3.y + b1.w, 0.0f));
    float* sp = (float*)&g_s4[(size_t)d * 2];
    asm volatile("red.global.add.v4.f32 [%0], {%1,%2,%3,%4};"
                 :: "l"(sp), "f"(x0), "f"(x1), "f"(x2), "f"(x3) : "memory");
    asm volatile("red.global.add.v4.f32 [%0], {%1,%2,%3,%4};"
                 :: "l"(sp + 4), "f"(x4), "f"(x5), "f"(x6), "f"(x7) : "memory");
    __half2 h01 = __floats2half2_rn(x0, x1);
    __half2 h23 = __floats2half2_rn(x2, x3);
    __half2 h45 = __floats2half2_rn(x4, x5);
    __half2 h67 = __floats2half2_rn(x6, x7);
    ulonglong2 packed;
    asm("mov.b64 %0, {%1, %2};" : "=l"(packed.x)
        : "r"(*(unsigned*)&h01), "r"(*(unsigned*)&h23));
    asm("mov.b64 %0, {%1, %2};" : "=l"(packed.y)
        : "r"(*(unsigned*)&h45), "r"(*(unsigned*)&h67));
    g_ex[e] = packed;   // coalesced STG.128
}

// ---------------------------------------------------------------------------
// K4 (finalize): out = ex / s[dst]. 1 thread/edge: dst once, ex one LDG.128,
// s[dst] one scattered 32B record, out 2x STG.128. Pure streaming otherwise.
// ---------------------------------------------------------------------------
__global__ void __launch_bounds__(256) finalize(const int* __restrict__ dst,
                                                float* __restrict__ out,
                                                int E) {
    int e = blockIdx.x * 256 + threadIdx.x;
    if (e >= E) return;
    int d = dst[e];
    ulonglong2 p = g_ex[e];
    float4 s0 = __ldg(&g_s4[(size_t)d * 2]);
    float4 s1 = __ldg(&g_s4[(size_t)d * 2 + 1]);
    unsigned a0, a1, a2, a3;
    asm("mov.b64 {%0, %1}, %2;" : "=r"(a0), "=r"(a1) : "l"(p.x));
    asm("mov.b64 {%0, %1}, %2;" : "=r"(a2), "=r"(a3) : "l"(p.y));
    float2 x01 = __half22float2(*(__half2*)&a0);
    float2 x23 = __half22float2(*(__half2*)&a1);
    float2 x45 = __half22float2(*(__half2*)&a2);
    float2 x67 = __half22float2(*(__half2*)&a3);
    float4 o0, o1;
    o0.x = __fdividef(x01.x, s0.x);
    o0.y = __fdividef(x01.y, s0.y);
    o0.z = __fdividef(x23.x, s0.z);
    o0.w = __fdividef(x23.y, s0.w);
    o1.x = __fdividef(x45.x, s1.x);
    o1.y = __fdividef(x45.y, s1.y);
    o1.z = __fdividef(x67.x, s1.z);
    o1.w = __fdividef(x67.y, s1.w);
    float4* po = (float4*)(out + (size_t)e * 8);
    po[0] = o0;
    po[1] = o1;
}

// ---------------------------------------------------------------------------
extern "C" void kernel_launch(void* const* d_in, const int* in_sizes, int n_in,
                              void* d_out, int out_size) {
    const float* feat     = (const float*)d_in[0];
    const int*   etype    = (const int*)  d_in[1];
    const int*   src      = (const int*)  d_in[2];
    const int*   dst      = (const int*)  d_in[3];
    const float* W_fc     = (const float*)d_in[4];
    const float* edge_emb = (const float*)d_in[5];
    const float* W_e      = (const float*)d_in[6];
    const float* attn_l   = (const float*)d_in[7];
    const float* attn_r   = (const float*)d_in[8];
    const float* attn_e   = (const float*)d_in[9];
    float* out = (float*)d_out;

    int N = in_sizes[0] / IN_F;
    int E = in_sizes[1];

    setup<<<IN_F + TMAX, 256>>>(W_fc, attn_l, attn_r, edge_emb, W_e, attn_e);
    node_proj<<<(N + 255) / 256, 128>>>(feat, N);
    edge_expsum<<<(E + 255) / 256, 256>>>(etype, src, dst, E);
    finalize<<<(E + 255) / 256, 256>>>(dst, out, E);
}